// round 4
// baseline (speedup 1.0000x reference)
#include <cuda_runtime.h>

// DWHT (buggy torch in-place semantics) + channel shuffle, fully fused.
// x: (64, 256, 28, 28) f32  ->  out: (64, 512, 28, 28) f32
//
// 8 passes = (F o F)^4.  G = F o F maps each aligned 16-channel chunk to a
// fixed signed output set (see compute_G).  Channel shuffle (groups=8):
// ch -> ((ch&63)<<3)|(ch>>6).
//
// Round-3 geometry: warp = 32 pixels x 1 chunk-lane; TRANSPOSED smem
// s[pixel][channel] with pitch 516 (== 4 mod 32) so the per-thread
// 32 consecutive-channel reads become 8 conflict-free LDS.128, and the
// scattered writes collapse into 4x STS.128 + 7x STS.64 + 2x STS.32.

#define NPIX   32
#define SPITCH 516   // floats per pixel row; %4==0 (alignment), %32==4 (banks)

struct GOut {
    float4 Al;            // -> 4*jl + q
    float2 Bl, Dl, Gl;    // -> 128+2jl, 256+2jl, 384+2jl
    float  El;            // -> 320+jl
    float4 Ah;            // -> 4*jh + q
    float4 Ch;            // -> 128+4jh + q
    float4 G4h;           // -> 384+4jh + q
    float2 Bh, Dh, G2h, Fh; // -> 128+2jh, 256+2jh, 384+2jh, 320+2jh
    float  Eh;            // -> 320+jh
};

__device__ __forceinline__ GOut compute_G(const float wl[16], const float wh[16]) {
    GOut o;
    // low chunk (jl)
    o.Al.x = wl[0]+wl[1]+wl[2]+wl[3];
    o.Al.y = wl[4]+wl[5]+wl[6]+wl[7];
    o.Al.z = wl[8]+wl[9]+wl[10]+wl[11];
    o.Al.w = wl[12]+wl[13]+wl[14]+wl[15];
    o.Bl.x = wl[0]+wl[1]-wl[2]-wl[3]+wl[4]+wl[5]-wl[6]-wl[7];
    o.Bl.y = wl[8]+wl[9]-wl[10]-wl[11]+wl[12]+wl[13]-wl[14]-wl[15];
    o.Dl.x = wl[0]+wl[1]+wl[2]+wl[3]-wl[4]-wl[5]-wl[6]-wl[7];
    o.Dl.y = wl[8]+wl[9]+wl[10]+wl[11]-wl[12]-wl[13]-wl[14]-wl[15];
    o.Gl.x = wl[0]+wl[1]-wl[2]-wl[3]-wl[4]-wl[5]+wl[6]+wl[7];
    o.Gl.y = wl[8]+wl[9]-wl[10]-wl[11]-wl[12]-wl[13]+wl[14]+wl[15];
    o.El   = wl[0]+wl[1]-wl[2]-wl[3]+wl[4]+wl[5]-wl[6]-wl[7]
            -wl[8]-wl[9]+wl[10]+wl[11]-wl[12]-wl[13]+wl[14]+wl[15];
    // high chunk (jh)
    o.Ah.x = wh[0]+wh[1]+wh[2]+wh[3];
    o.Ah.y = wh[4]+wh[5]+wh[6]+wh[7];
    o.Ah.z = wh[8]+wh[9]+wh[10]+wh[11];
    o.Ah.w = wh[12]+wh[13]+wh[14]+wh[15];
    o.Ch.x = wh[0]-wh[1]+wh[2]-wh[3];
    o.Ch.y = wh[4]-wh[5]+wh[6]-wh[7];
    o.Ch.z = wh[8]-wh[9]+wh[10]-wh[11];
    o.Ch.w = wh[12]-wh[13]+wh[14]-wh[15];
    o.G4h.x = wh[0]-wh[1]-wh[2]+wh[3];
    o.G4h.y = wh[4]-wh[5]-wh[6]+wh[7];
    o.G4h.z = wh[8]-wh[9]-wh[10]+wh[11];
    o.G4h.w = wh[12]-wh[13]-wh[14]+wh[15];
    o.Bh.x = wh[0]+wh[1]-wh[2]-wh[3]+wh[4]+wh[5]-wh[6]-wh[7];
    o.Bh.y = wh[8]+wh[9]-wh[10]-wh[11]+wh[12]+wh[13]-wh[14]-wh[15];
    o.Dh.x = wh[0]+wh[1]+wh[2]+wh[3]-wh[4]-wh[5]-wh[6]-wh[7];
    o.Dh.y = wh[8]+wh[9]+wh[10]+wh[11]-wh[12]-wh[13]-wh[14]-wh[15];
    o.G2h.x = wh[0]+wh[1]-wh[2]-wh[3]-wh[4]-wh[5]+wh[6]+wh[7];
    o.G2h.y = wh[8]+wh[9]-wh[10]-wh[11]-wh[12]-wh[13]+wh[14]+wh[15];
    o.Fh.x = wh[0]-wh[1]+wh[2]-wh[3]-wh[4]+wh[5]-wh[6]+wh[7];
    o.Fh.y = wh[8]-wh[9]+wh[10]-wh[11]-wh[12]+wh[13]-wh[14]+wh[15];
    o.Eh   = wh[0]+wh[1]-wh[2]-wh[3]+wh[4]+wh[5]-wh[6]-wh[7]
            -wh[8]-wh[9]+wh[10]+wh[11]-wh[12]-wh[13]+wh[14]+wh[15];
    return o;
}

// Vectorized scatter of one G-stage into the transposed smem row.
__device__ __forceinline__ void store_G(float* __restrict__ sp, int jl, const GOut& o) {
    const int jh = jl + 16;
    *(float4*)(sp + 4*jl)        = o.Al;
    *(float2*)(sp + 128 + 2*jl)  = o.Bl;
    *(float2*)(sp + 256 + 2*jl)  = o.Dl;
    *(float2*)(sp + 384 + 2*jl)  = o.Gl;
    sp[320 + jl]                 = o.El;
    *(float4*)(sp + 4*jh)        = o.Ah;
    *(float4*)(sp + 128 + 4*jh)  = o.Ch;
    *(float4*)(sp + 384 + 4*jh)  = o.G4h;
    *(float2*)(sp + 128 + 2*jh)  = o.Bh;
    *(float2*)(sp + 256 + 2*jh)  = o.Dh;
    *(float2*)(sp + 384 + 2*jh)  = o.G2h;
    *(float2*)(sp + 320 + 2*jh)  = o.Fh;
    sp[320 + jh]                 = o.Eh;
}

__device__ __forceinline__ void load_G(const float* __restrict__ sp, int jl,
                                       float wl[16], float wh[16]) {
    const int jh = jl + 16;
#pragma unroll
    for (int v = 0; v < 4; v++) {
        float4 a = *(const float4*)(sp + 16*jl + 4*v);
        wl[4*v+0] = a.x; wl[4*v+1] = a.y; wl[4*v+2] = a.z; wl[4*v+3] = a.w;
        float4 b = *(const float4*)(sp + 16*jh + 4*v);
        wh[4*v+0] = b.x; wh[4*v+1] = b.y; wh[4*v+2] = b.z; wh[4*v+3] = b.w;
    }
}

// Store one channel's value to global with the groups=8 shuffle applied.
__device__ __forceinline__ void gstore(float* __restrict__ op, int idx, float v) {
    const int c = ((idx & 63) << 3) | (idx >> 6);
    op[c * 784] = v;
}

__global__ __launch_bounds__(512, 3)
void dwht_kernel(const float* __restrict__ x, float* __restrict__ out) {
    extern __shared__ float s[];   // [NPIX][SPITCH]

    const int tid = threadIdx.x;
    const int p   = tid & (NPIX - 1);   // pixel lane within warp   [0,32)
    const int jl  = tid >> 5;           // chunk pair id = warp id  [0,16)
    const int jh  = jl + 16;
    float* sp = s + p * SPITCH;

    const int b    = blockIdx.x / 25;
    const int hw   = (blockIdx.x % 25) * NPIX + p;
    const bool valid = (hw < 784);
    const float* xp = x   + (size_t)b * (256 * 784) + hw;
    float*       op = out + (size_t)b * (512 * 784) + hw;

    float wl[16], wh[16];

    // ---- stage 1: global load (upper 256 channels are the zero pad) ----
#pragma unroll
    for (int m = 0; m < 16; m++) wl[m] = valid ? xp[(16 * jl + m) * 784] : 0.0f;
#pragma unroll
    for (int m = 0; m < 16; m++) wh[m] = 0.0f;
    store_G(sp, jl, compute_G(wl, wh));
    __syncthreads();

    // ---- stages 2 & 3: smem -> registers -> smem ----
#pragma unroll
    for (int st = 0; st < 2; st++) {
        load_G(sp, jl, wl, wh);
        GOut o = compute_G(wl, wh);
        __syncthreads();   // all reads done before anyone overwrites
        store_G(sp, jl, o);
        __syncthreads();
    }

    // ---- stage 4: smem -> registers -> shuffled global store ----
    load_G(sp, jl, wl, wh);
    GOut o = compute_G(wl, wh);
    if (valid) {
        gstore(op, 4*jl+0, o.Al.x); gstore(op, 4*jl+1, o.Al.y);
        gstore(op, 4*jl+2, o.Al.z); gstore(op, 4*jl+3, o.Al.w);
        gstore(op, 128+2*jl+0, o.Bl.x); gstore(op, 128+2*jl+1, o.Bl.y);
        gstore(op, 256+2*jl+0, o.Dl.x); gstore(op, 256+2*jl+1, o.Dl.y);
        gstore(op, 384+2*jl+0, o.Gl.x); gstore(op, 384+2*jl+1, o.Gl.y);
        gstore(op, 320+jl, o.El);
        gstore(op, 4*jh+0, o.Ah.x); gstore(op, 4*jh+1, o.Ah.y);
        gstore(op, 4*jh+2, o.Ah.z); gstore(op, 4*jh+3, o.Ah.w);
        gstore(op, 128+4*jh+0, o.Ch.x); gstore(op, 128+4*jh+1, o.Ch.y);
        gstore(op, 128+4*jh+2, o.Ch.z); gstore(op, 128+4*jh+3, o.Ch.w);
        gstore(op, 384+4*jh+0, o.G4h.x); gstore(op, 384+4*jh+1, o.G4h.y);
        gstore(op, 384+4*jh+2, o.G4h.z); gstore(op, 384+4*jh+3, o.G4h.w);
        gstore(op, 128+2*jh+0, o.Bh.x); gstore(op, 128+2*jh+1, o.Bh.y);
        gstore(op, 256+2*jh+0, o.Dh.x); gstore(op, 256+2*jh+1, o.Dh.y);
        gstore(op, 384+2*jh+0, o.G2h.x); gstore(op, 384+2*jh+1, o.G2h.y);
        gstore(op, 320+2*jh+0, o.Fh.x); gstore(op, 320+2*jh+1, o.Fh.y);
        gstore(op, 320+jh, o.Eh);
    }
}

extern "C" void kernel_launch(void* const* d_in, const int* in_sizes, int n_in,
                              void* d_out, int out_size) {
    const float* x = (const float*)d_in[0];
    float* out = (float*)d_out;
    const int smem = NPIX * SPITCH * sizeof(float);   // 66,048 B
    static bool attr_set = false;                     // idempotent host-side attr
    if (!attr_set) {
        cudaFuncSetAttribute(dwht_kernel,
                             cudaFuncAttributeMaxDynamicSharedMemorySize, smem);
        attr_set = true;
    }
    // 64 images * 25 pixel-tiles of 32 (last tile predicated: 784 = 24*32+16)
    dwht_kernel<<<64 * 25, 512, smem>>>(x, out);
}

// round 5
// speedup vs baseline: 1.1682x; 1.1682x over previous
#include <cuda_runtime.h>

// DWHT (buggy torch in-place semantics) + channel shuffle, fully fused.
// x: (64, 256, 28, 28) f32  ->  out: (64, 512, 28, 28) f32
//
// 8 passes = (F o F)^4.  G = F o F maps each aligned 16-channel chunk to a
// fixed signed output set.  Channel shuffle (groups=8): ch->((ch&63)<<3)|(ch>>6).
//
// Layout (best measured, R2): warp = 32 pixels x 1 chunk-pair, smem
// s[channel][pixel] (pitch 32) -> EVERY scalar LDS/STS is bank-conflict-free
// (fixed channel per instruction, p=0..31 spans all banks). 64KB dynamic smem.
//
// Round-5 addition: zero-pad sparsity. After stage 1 only the low-family
// channels are nonzero -> chunks {0,1,2,3,8,9,16,17,20,24,25}. Stage 1 stores
// only its 11 low outputs; stage 2 reads only those chunks (warp-uniform
// skip); after stage 2 chunks {1,3,7,15,31} are still zero, so stage 3 skips
// those reads. Cuts smem crossbar traffic ~25%.

#define NPIX 32

__device__ __forceinline__ void butterfly2(const float wl[16], const float wh[16],
                                           float o[32]) {
    int n = 0;
#pragma unroll
    for (int q = 0; q < 4; q++)
        o[n++] = wl[4*q+0] + wl[4*q+1] + wl[4*q+2] + wl[4*q+3];            // A (low)
#pragma unroll
    for (int r = 0; r < 2; r++) {
        const float a0 = wl[8*r+0], a1 = wl[8*r+1], a2 = wl[8*r+2], a3 = wl[8*r+3];
        const float a4 = wl[8*r+4], a5 = wl[8*r+5], a6 = wl[8*r+6], a7 = wl[8*r+7];
        o[n++] = a0+a1-a2-a3+a4+a5-a6-a7;                                  // B (low)
        o[n++] = a0+a1+a2+a3-a4-a5-a6-a7;                                  // D (low)
        o[n++] = a0+a1-a2-a3-a4-a5+a6+a7;                                  // G2a (low)
    }
    o[n++] = wl[0]+wl[1]-wl[2]-wl[3]+wl[4]+wl[5]-wl[6]-wl[7]
            -wl[8]-wl[9]+wl[10]+wl[11]-wl[12]-wl[13]+wl[14]+wl[15];        // E (low)
#pragma unroll
    for (int q = 0; q < 4; q++) {
        const float b0 = wh[4*q+0], b1 = wh[4*q+1], b2 = wh[4*q+2], b3 = wh[4*q+3];
        o[n++] = b0+b1+b2+b3;                                              // A (high)
        o[n++] = b0-b1+b2-b3;                                              // C
        o[n++] = b0-b1-b2+b3;                                              // G2b
    }
#pragma unroll
    for (int r = 0; r < 2; r++) {
        const float b0 = wh[8*r+0], b1 = wh[8*r+1], b2 = wh[8*r+2], b3 = wh[8*r+3];
        const float b4 = wh[8*r+4], b5 = wh[8*r+5], b6 = wh[8*r+6], b7 = wh[8*r+7];
        o[n++] = b0+b1-b2-b3+b4+b5-b6-b7;                                  // B (high)
        o[n++] = b0+b1+b2+b3-b4-b5-b6-b7;                                  // D (high)
        o[n++] = b0+b1-b2-b3-b4-b5+b6+b7;                                  // G2a (high)
        o[n++] = b0-b1+b2-b3-b4+b5-b6+b7;                                  // F2
    }
    o[n++] = wh[0]+wh[1]-wh[2]-wh[3]+wh[4]+wh[5]-wh[6]-wh[7]
            -wh[8]-wh[9]+wh[10]+wh[11]-wh[12]-wh[13]+wh[14]+wh[15];        // E (high)
}

// Canonical index order matches butterfly2's fill order. The first 11 entries
// (n < 11) are exactly the low-family outputs.
template <typename PUT>
__device__ __forceinline__ void emit_indices(int jl, PUT put) {
    const int jh = jl + 16;
    int n = 0;
#pragma unroll
    for (int q = 0; q < 4; q++) put(n++, 4*jl + q);
#pragma unroll
    for (int r = 0; r < 2; r++) {
        put(n++, 128 + 2*jl + r);
        put(n++, 256 + 2*jl + r);
        put(n++, 384 + 2*jl + r);
    }
    put(n++, 320 + jl);
#pragma unroll
    for (int q = 0; q < 4; q++) {
        put(n++,   4*jh + q);
        put(n++, 128 + 4*jh + q);
        put(n++, 384 + 4*jh + q);
    }
#pragma unroll
    for (int r = 0; r < 2; r++) {
        put(n++, 128 + 2*jh + r);
        put(n++, 256 + 2*jh + r);
        put(n++, 384 + 2*jh + r);
        put(n++, 320 + 2*jh + r);
    }
    put(n++, 320 + jh);
}

__global__ __launch_bounds__(512, 3)
void dwht_kernel(const float* __restrict__ x, float* __restrict__ out) {
    extern __shared__ float s[];   // [512][NPIX] = 64 KB, channel-major

    const int tid = threadIdx.x;
    const int p   = tid & (NPIX - 1);   // pixel lane within warp   [0,32)
    const int jl  = tid >> 5;           // chunk pair id = warp id  [0,16)
    const int jh  = jl + 16;

    const int b    = blockIdx.x / 25;
    const int hw   = (blockIdx.x % 25) * NPIX + p;
    const bool valid = (hw < 784);
    const float* xp = x   + (size_t)b * (256 * 784) + hw;
    float*       op = out + (size_t)b * (512 * 784) + hw;

    float wl[16], wh[16], o[32];

    // ---- stage 1: global load (upper 256 channels are the zero pad) ----
#pragma unroll
    for (int m = 0; m < 16; m++) wl[m] = valid ? xp[(16 * jl + m) * 784] : 0.0f;
#pragma unroll
    for (int m = 0; m < 16; m++) wh[m] = 0.0f;

    butterfly2(wl, wh, o);
    // Only the 11 low-family outputs are nonzero; stage 2 never reads the rest.
    emit_indices(jl, [&](int n, int idx) {
        if (n < 11) s[idx * NPIX + p] = o[n];
    });
    __syncthreads();

    // ---- stage 2: only chunks {0,1,2,3,8,9,16,17,20,24,25} are nonzero ----
    {
        const bool rl = (jl <= 3) | (jl == 8) | (jl == 9);          // chunk jl
        const bool rh = (jl <= 1) | (jl == 4) | (jl == 8) | (jl == 9); // chunk jl+16
        if (rl) {
#pragma unroll
            for (int m = 0; m < 16; m++) wl[m] = s[(16 * jl + m) * NPIX + p];
        } else {
#pragma unroll
            for (int m = 0; m < 16; m++) wl[m] = 0.0f;
        }
        if (rh) {
#pragma unroll
            for (int m = 0; m < 16; m++) wh[m] = s[(16 * jh + m) * NPIX + p];
        } else {
#pragma unroll
            for (int m = 0; m < 16; m++) wh[m] = 0.0f;
        }
        butterfly2(wl, wh, o);
        __syncthreads();   // all reads done before anyone overwrites
        emit_indices(jl, [&](int n, int idx) { s[idx * NPIX + p] = o[n]; });
        __syncthreads();
    }

    // ---- stage 3: chunks {1,3,7,15,31} are still identically zero ----
    {
        const bool rl = !((jl == 1) | (jl == 3) | (jl == 7) | (jl == 15));
        const bool rh = (jl != 15);   // jh==31 is zero
        if (rl) {
#pragma unroll
            for (int m = 0; m < 16; m++) wl[m] = s[(16 * jl + m) * NPIX + p];
        } else {
#pragma unroll
            for (int m = 0; m < 16; m++) wl[m] = 0.0f;
        }
        if (rh) {
#pragma unroll
            for (int m = 0; m < 16; m++) wh[m] = s[(16 * jh + m) * NPIX + p];
        } else {
#pragma unroll
            for (int m = 0; m < 16; m++) wh[m] = 0.0f;
        }
        butterfly2(wl, wh, o);
        __syncthreads();
        emit_indices(jl, [&](int n, int idx) { s[idx * NPIX + p] = o[n]; });
        __syncthreads();
    }

    // ---- stage 4: smem -> registers -> shuffled global store ----
#pragma unroll
    for (int m = 0; m < 16; m++) wl[m] = s[(16 * jl + m) * NPIX + p];
#pragma unroll
    for (int m = 0; m < 16; m++) wh[m] = s[(16 * jh + m) * NPIX + p];
    butterfly2(wl, wh, o);
    if (valid) {
        emit_indices(jl, [&](int n, int idx) {
            const int c = ((idx & 63) << 3) | (idx >> 6);   // groups=8 shuffle
            op[c * 784] = o[n];
        });
    }
}

extern "C" void kernel_launch(void* const* d_in, const int* in_sizes, int n_in,
                              void* d_out, int out_size) {
    const float* x = (const float*)d_in[0];
    float* out = (float*)d_out;
    const int smem = 512 * NPIX * sizeof(float);   // 64 KB
    static bool attr_set = false;                  // idempotent host-side attr
    if (!attr_set) {
        cudaFuncSetAttribute(dwht_kernel,
                             cudaFuncAttributeMaxDynamicSharedMemorySize, smem);
        attr_set = true;
    }
    // 64 images * 25 pixel-tiles of 32 (last tile predicated: 784 = 24*32+16)
    dwht_kernel<<<64 * 25, 512, smem>>>(x, out);
}